// round 16
// baseline (speedup 1.0000x reference)
#include <cuda_runtime.h>
#include <cuda_bf16.h>
#include <cuda_fp16.h>
#include <cstdint>
#include <math.h>

#define NNODES 20000
#define NEDGES 320000
#define NREL 3
#define FDIM 128
#define NEG_SLOPE 0.2f
#define CAP 96          // bucket capacity per (relation, dst)
#define MTILES 3        // M-tiles per GEMM CTA

// ---------------- scratch (static device globals; no allocation) ----------------
__device__ __half g_fh[(size_t)NREL * NNODES * FDIM];   // f in fp16 (gather payload)
__device__ float g_z[(size_t)NREL * NNODES * FDIM];
__device__ float g_el[NREL * NNODES * 2];
__device__ float g_er[NREL * NNODES * 2];
__device__ int   g_deg[NREL * NNODES];
__device__ int   g_bkt[(size_t)NREL * NNODES * CAP];
__device__ float g_wsum[2 * NREL];
// bf16 split operands
__device__ __nv_bfloat16 g_ahi[(size_t)NNODES * FDIM];
__device__ __nv_bfloat16 g_alo[(size_t)NNODES * FDIM];
__device__ __nv_bfloat16 g_whi[2 * NREL * FDIM * FDIM];   // [layer][r][n][k]
__device__ __nv_bfloat16 g_wlo[2 * NREL * FDIM * FDIM];

// ---------------- fused bucket build ----------------
__global__ void k_build(const int* __restrict__ edges) {
    int r = blockIdx.y;
    int t = blockIdx.x * blockDim.x + threadIdx.x;
    if (t >= NEDGES / 4) return;
    const int4 s4 = *(const int4*)(edges + (size_t)(r * 2 + 0) * NEDGES + 4 * t);
    const int4 d4 = *(const int4*)(edges + (size_t)(r * 2 + 1) * NEDGES + 4 * t);
    int base = r * NNODES;
    int p0 = atomicAdd(&g_deg[base + d4.x], 1);
    int p1 = atomicAdd(&g_deg[base + d4.y], 1);
    int p2 = atomicAdd(&g_deg[base + d4.z], 1);
    int p3 = atomicAdd(&g_deg[base + d4.w], 1);
    g_bkt[(size_t)(base + d4.x) * CAP + p0] = s4.x;
    g_bkt[(size_t)(base + d4.y) * CAP + p1] = s4.y;
    g_bkt[(size_t)(base + d4.z) * CAP + p2] = s4.z;
    g_bkt[(size_t)(base + d4.w) * CAP + p3] = s4.w;
}

// ---------------- bf16 split conversion ----------------
__global__ void k_cvtA(const float* __restrict__ src,
                       __nv_bfloat16* __restrict__ hi, __nv_bfloat16* __restrict__ lo) {
    int i = blockIdx.x * blockDim.x + threadIdx.x;
    if (i >= NNODES * 32) return;
    float4 v = ((const float4*)src)[i];
    __nv_bfloat16 h0 = __float2bfloat16(v.x), h1 = __float2bfloat16(v.y);
    __nv_bfloat16 h2 = __float2bfloat16(v.z), h3 = __float2bfloat16(v.w);
    ((__nv_bfloat162*)hi)[2 * i]     = __nv_bfloat162(h0, h1);
    ((__nv_bfloat162*)hi)[2 * i + 1] = __nv_bfloat162(h2, h3);
    ((__nv_bfloat162*)lo)[2 * i]     = __nv_bfloat162(
        __float2bfloat16(v.x - __bfloat162float(h0)), __float2bfloat16(v.y - __bfloat162float(h1)));
    ((__nv_bfloat162*)lo)[2 * i + 1] = __nv_bfloat162(
        __float2bfloat16(v.z - __bfloat162float(h2)), __float2bfloat16(v.w - __bfloat162float(h3)));
}

__global__ void k_cvtW(const float* __restrict__ W1, const float* __restrict__ W2,
                       __nv_bfloat16* __restrict__ hi, __nv_bfloat16* __restrict__ lo) {
    int idx = blockIdx.x * blockDim.x + threadIdx.x;
    if (idx >= 2 * NREL * FDIM * FDIM) return;
    int l = idx / (NREL * FDIM * FDIM);
    int rem = idx - l * (NREL * FDIM * FDIM);
    int r = rem >> 14;
    int n = (rem >> 7) & 127, k = rem & 127;
    const float* W = l ? W2 : W1;
    float v = W[r * 16384 + k * 128 + n];
    __nv_bfloat16 h = __float2bfloat16(v);
    hi[idx] = h;
    lo[idx] = __float2bfloat16(v - __bfloat162float(h));
}

// ---------------- mma.sync GEMM: W resident, M-loop with double-buffered A ----------------
#define ASTRIDE 136
#define TILEB  (128 * ASTRIDE)
#define TILEBYTES (TILEB * 2)
// smem: [Wh][Wl][A0h][A0l][A1h][A1l][s_al][s_ar]
#define SMEM_GEMM (6 * TILEBYTES + 2 * 128 * 4)

__device__ __forceinline__ uint32_t smem_u32(const void* p) {
    uint32_t a;
    asm("{ .reg .u64 t; cvta.to.shared.u64 t, %1; cvt.u32.u64 %0, t; }" : "=r"(a) : "l"(p));
    return a;
}
__device__ __forceinline__ void cp16(uint32_t dst, const void* src, int sz) {
    asm volatile("cp.async.cg.shared.global [%0], [%1], 16, %2;"
                 :: "r"(dst), "l"(src), "r"(sz));
}
__device__ __forceinline__ void ldsm_x4(uint32_t addr, uint32_t& r0, uint32_t& r1,
                                        uint32_t& r2, uint32_t& r3) {
    asm volatile("ldmatrix.sync.aligned.m8n8.x4.shared.b16 {%0,%1,%2,%3}, [%4];"
                 : "=r"(r0), "=r"(r1), "=r"(r2), "=r"(r3) : "r"(addr));
}
__device__ __forceinline__ void ldsm_x2(uint32_t addr, uint32_t& r0, uint32_t& r1) {
    asm volatile("ldmatrix.sync.aligned.m8n8.x2.shared.b16 {%0,%1}, [%2];"
                 : "=r"(r0), "=r"(r1) : "r"(addr));
}
__device__ __forceinline__ void mma16816(float* c, uint32_t a0, uint32_t a1, uint32_t a2,
                                         uint32_t a3, uint32_t b0, uint32_t b1) {
    asm volatile(
        "mma.sync.aligned.m16n8k16.row.col.f32.bf16.bf16.f32 "
        "{%0,%1,%2,%3}, {%4,%5,%6,%7}, {%8,%9}, {%0,%1,%2,%3};"
        : "+f"(c[0]), "+f"(c[1]), "+f"(c[2]), "+f"(c[3])
        : "r"(a0), "r"(a1), "r"(a2), "r"(a3), "r"(b0), "r"(b1));
}

// 512 threads = 16 warps: 8 M-warps x 2 N-warps. Warp tile 16 rows x 64 cols.
// grid (ceil(157/3)=53, NREL). W loaded once per CTA; A double-buffered.
__global__ void __launch_bounds__(512) k_gemm_mma(
    const __nv_bfloat16* __restrict__ ahi, const __nv_bfloat16* __restrict__ alo,
    const __nv_bfloat16* __restrict__ whi, const __nv_bfloat16* __restrict__ wlo,
    const float* __restrict__ alv, const float* __restrict__ arv,
    __half* __restrict__ fh_base, float* __restrict__ el_base, float* __restrict__ er_base) {
    extern __shared__ char smem[];
    __nv_bfloat16* Wh = (__nv_bfloat16*)smem;
    __nv_bfloat16* Wl = Wh + TILEB;
    __nv_bfloat16* Abuf = Wl + TILEB;                 // 2 buffers x (Ah, Al)
    float* s_al = (float*)(smem + 6 * TILEBYTES);
    float* s_ar = s_al + 128;
    uint32_t sb = smem_u32(smem);

    int tid = threadIdx.x;
    int wid = tid >> 5, lane = tid & 31;
    int wid_m = wid & 7, wid_n = wid >> 3;
    int r = blockIdx.y;
    int tile0 = blockIdx.x * MTILES;

    __half* fh = fh_base + (size_t)r * NNODES * FDIM;
    float* el = el_base + r * NNODES * 2;
    float* er = er_base + r * NNODES * 2;

    if (tid < 128) { s_al[tid] = alv[r * 128 + tid]; s_ar[tid] = arv[r * 128 + tid]; }

    const __nv_bfloat16* wh = whi + (size_t)r * 16384;
    const __nv_bfloat16* wl = wlo + (size_t)r * 16384;

    // ---- fill W once ----
    for (int c = tid; c < 2048; c += 512) {
        int row = c >> 4;
        int col = (c & 15) << 3;
        uint32_t soff = (uint32_t)(row * ASTRIDE + col) * 2;
        cp16(sb + soff,             wh + row * 128 + col, 16);
        cp16(sb + TILEBYTES + soff, wl + row * 128 + col, 16);
    }
    // ---- fill A(tile0) into buf 0 ----
    {
        int m0 = tile0 * 128;
        uint32_t ab = sb + 2 * TILEBYTES;
        for (int c = tid; c < 2048; c += 512) {
            int row = c >> 4;
            int col = (c & 15) << 3;
            int gm = m0 + row;
            int sz = (gm < NNODES) ? 16 : 0;
            int gmc = (gm < NNODES) ? gm : (NNODES - 1);
            uint32_t soff = (uint32_t)(row * ASTRIDE + col) * 2;
            cp16(ab + soff,             ahi + (size_t)gmc * 128 + col, sz);
            cp16(ab + TILEBYTES + soff, alo + (size_t)gmc * 128 + col, sz);
        }
    }
    asm volatile("cp.async.commit_group;");
    asm volatile("cp.async.wait_group 0;" ::: "memory");
    __syncthreads();

    uint32_t b_row = (uint32_t)(wid_n * 64 + (lane & 7));
    uint32_t b_colsel = (uint32_t)(((lane >> 3) & 1) << 3);
    uint32_t a_row = (uint32_t)(wid_m * 16 + (lane & 15));
    uint32_t a_colsel = (uint32_t)((lane >> 4) << 3);
    int m_base = wid_m * 16;
    int cb = wid_n * 64;

    for (int mt = 0; mt < MTILES; mt++) {
        // prefetch next A tile into other buffer
        if (mt + 1 < MTILES) {
            int m0n = (tile0 + mt + 1) * 128;
            uint32_t ab = sb + 2 * TILEBYTES + ((mt + 1) & 1) * 2 * TILEBYTES;
            for (int c = tid; c < 2048; c += 512) {
                int row = c >> 4;
                int col = (c & 15) << 3;
                int gm = m0n + row;
                int sz = (gm < NNODES) ? 16 : 0;
                int gmc = (gm < NNODES) ? gm : (NNODES - 1);
                uint32_t soff = (uint32_t)(row * ASTRIDE + col) * 2;
                cp16(ab + soff,             ahi + (size_t)gmc * 128 + col, sz);
                cp16(ab + TILEBYTES + soff, alo + (size_t)gmc * 128 + col, sz);
            }
            asm volatile("cp.async.commit_group;");
        }

        // ---- compute current tile ----
        int m0 = (tile0 + mt) * 128;
        __nv_bfloat16* Ah = Abuf + (mt & 1) * 2 * TILEB;
        __nv_bfloat16* Al = Ah + TILEB;

        float acc[8][4];
#pragma unroll
        for (int nt = 0; nt < 8; nt++)
#pragma unroll
            for (int j = 0; j < 4; j++) acc[nt][j] = 0.f;

#pragma unroll
        for (int t = 0; t < 3; t++) {
            const __nv_bfloat16* As = (t < 2) ? Ah : Al;
            const __nv_bfloat16* Bs = (t == 1) ? Wl : Wh;
            uint32_t a_base = smem_u32(As + a_row * ASTRIDE + a_colsel);
            uint32_t b_base = smem_u32(Bs + b_row * ASTRIDE + b_colsel);
#pragma unroll
            for (int kk = 0; kk < 8; kk++) {
                uint32_t a0, a1, a2, a3;
                ldsm_x4(a_base + kk * 32, a0, a1, a2, a3);
#pragma unroll
                for (int nt = 0; nt < 8; nt++) {
                    uint32_t b0, b1;
                    ldsm_x2(b_base + (uint32_t)(nt * 8 * ASTRIDE * 2) + kk * 32, b0, b1);
                    mma16816(acc[nt], a0, a1, a2, a3, b0, b1);
                }
            }
        }

        // ---- epilogue ----
        int q = lane & 3;
        int r0 = m_base + (lane >> 2);
        int r1 = r0 + 8;
        int gm0 = m0 + r0, gm1 = m0 + r1;
        float elA = 0.f, erA = 0.f, elB = 0.f, erB = 0.f;
#pragma unroll
        for (int nt = 0; nt < 8; nt++) {
            int c0 = cb + nt * 8 + q * 2;
            float a0 = s_al[c0], a1 = s_al[c0 + 1];
            float b0 = s_ar[c0], b1 = s_ar[c0 + 1];
            elA += acc[nt][0] * a0 + acc[nt][1] * a1;
            elB += acc[nt][2] * a0 + acc[nt][3] * a1;
            erA += acc[nt][0] * b0 + acc[nt][1] * b1;
            erB += acc[nt][2] * b0 + acc[nt][3] * b1;
            if (gm0 < NNODES)
                *(__half2*)(fh + (size_t)gm0 * 128 + c0) =
                    __float22half2_rn(make_float2(acc[nt][0], acc[nt][1]));
            if (gm1 < NNODES)
                *(__half2*)(fh + (size_t)gm1 * 128 + c0) =
                    __float22half2_rn(make_float2(acc[nt][2], acc[nt][3]));
        }
#pragma unroll
        for (int o = 1; o <= 2; o <<= 1) {
            elA += __shfl_xor_sync(0xffffffffu, elA, o);
            erA += __shfl_xor_sync(0xffffffffu, erA, o);
            elB += __shfl_xor_sync(0xffffffffu, elB, o);
            erB += __shfl_xor_sync(0xffffffffu, erB, o);
        }
        if (q == 0) {
            if (gm0 < NNODES) { el[2 * gm0 + wid_n] = elA; er[2 * gm0 + wid_n] = erA; }
            if (gm1 < NNODES) { el[2 * gm1 + wid_n] = elB; er[2 * gm1 + wid_n] = erB; }
        }

        if (mt + 1 < MTILES) {
            asm volatile("cp.async.wait_group 0;" ::: "memory");
            __syncthreads();
        }
    }
}

// ---------------- GAT aggregation + fused semantic score (1024-thread blocks) ----------------
// smem: w1 16384 | b1 128 | w2 128 | part 128 | src 12288 | wgt 24576 | z 16384
#define AG_W1   0
#define AG_B1   16384
#define AG_W2   16512
#define AG_PART 16640
#define AG_SRC  16768
#define AG_WGT  (16768 + 12288)
#define AG_Z    (16768 + 12288 + 24576)
#define SMEM_AGG (AG_Z + 16384)

__global__ void __launch_bounds__(1024) k_aggsc(
    const __half* __restrict__ fh_base, const float* __restrict__ el_base,
    const float* __restrict__ er_base, const float* __restrict__ bias_base,
    const float* __restrict__ w1, const float* __restrict__ bb,
    const float* __restrict__ w2, float* __restrict__ wsum,
    float* __restrict__ z_base, int do_relu) {
    extern __shared__ char sm[];
    float* s_w1  = (float*)(sm + AG_W1);
    float* s_b1  = (float*)(sm + AG_B1);
    float* s_w2  = (float*)(sm + AG_W2);
    float* s_part= (float*)(sm + AG_PART);
    int*   s_src = (int*)(sm + AG_SRC);
    float* s_wgt = (float*)(sm + AG_WGT);
    float* s_z   = (float*)(sm + AG_Z);

    int r = blockIdx.y;
    const __half* fh = fh_base + (size_t)r * NNODES * FDIM;
    const float* el  = el_base + r * NNODES * 2;
    const float* er  = er_base + r * NNODES * 2;
    const float* bias = bias_base + r * 128;
    float* z = z_base + (size_t)r * NNODES * FDIM;

    int tid = threadIdx.x;
    ((float4*)s_w1)[tid] = ((const float4*)w1)[tid];     // 1024 float4 = 4096 floats
    if (tid < 32) { s_b1[tid] = bb[tid]; s_w2[tid] = w2[tid]; }
    __syncthreads();

    int wid = tid >> 5, lane = tid & 31;
    int n = blockIdx.x * 32 + wid;
    int deg = g_deg[r * NNODES + n];
    const int* bkt = &g_bkt[(size_t)(r * NNODES + n) * CAP];
    float er0 = er[2 * n], er1 = er[2 * n + 1];

    // ---- phase A: per-edge weights, lane-parallel ----
    float den0 = 0.f, den1 = 0.f;
    for (int i = lane; i < deg; i += 32) {
        int s = bkt[i];
        float2 ev = *(const float2*)(el + 2 * s);
        float e0 = ev.x + er0; e0 = e0 > 0.f ? e0 : NEG_SLOPE * e0;
        float e1 = ev.y + er1; e1 = e1 > 0.f ? e1 : NEG_SLOPE * e1;
        float w0 = __expf(e0), w1v = __expf(e1);
        s_src[wid * CAP + i] = s;
        s_wgt[(wid * 2 + 0) * CAP + i] = w0;
        s_wgt[(wid * 2 + 1) * CAP + i] = w1v;
        den0 += w0; den1 += w1v;
    }
#pragma unroll
    for (int o = 16; o; o >>= 1) {
        den0 += __shfl_xor_sync(0xffffffffu, den0, o);
        den1 += __shfl_xor_sync(0xffffffffu, den1, o);
    }
    __syncwarp();

    // ---- phase B: serial accumulate, 8B fp16 gathers ----
    int myh = lane >> 4;
    const float* wgt = &s_wgt[(wid * 2 + myh) * CAP];
    const int* src = &s_src[wid * CAP];
    float4 acc = make_float4(0.f, 0.f, 0.f, 0.f);
#pragma unroll 4
    for (int i = 0; i < deg; i++) {
        int s = src[i];
        float w = wgt[i];
        uint2 raw = *(const uint2*)(fh + (size_t)s * 128 + lane * 4);
        float2 a = __half22float2(*(const __half2*)&raw.x);
        float2 b = __half22float2(*(const __half2*)&raw.y);
        acc.x += w * a.x; acc.y += w * a.y; acc.z += w * b.x; acc.w += w * b.y;
    }
    float den = myh ? den1 : den0;
    float scale = 1.f / fmaxf(den, 1e-9f);
    float4 bv = *(const float4*)(bias + lane * 4);
    float4 o;
    o.x = acc.x * scale + bv.x;
    o.y = acc.y * scale + bv.y;
    o.z = acc.z * scale + bv.z;
    o.w = acc.w * scale + bv.w;
    if (do_relu) {
        o.x = fmaxf(o.x, 0.f); o.y = fmaxf(o.y, 0.f);
        o.z = fmaxf(o.z, 0.f); o.w = fmaxf(o.w, 0.f);
    }
    *(float4*)(z + (size_t)n * 128 + lane * 4) = o;

    // ---- fused semantic score: z staged in smem (warp-local), no shfl ----
    *(float4*)(s_z + wid * 128 + lane * 4) = o;
    __syncwarp();
    float sacc = 0.f;
    const float* zrow = s_z + wid * 128;
#pragma unroll
    for (int k4 = 0; k4 < 32; k4++) {
        float4 zv = *(const float4*)(zrow + k4 * 4);
        sacc += zv.x * s_w1[(k4 * 4 + 0) * 32 + lane]
              + zv.y * s_w1[(k4 * 4 + 1) * 32 + lane]
              + zv.z * s_w1[(k4 * 4 + 2) * 32 + lane]
              + zv.w * s_w1[(k4 * 4 + 3) * 32 + lane];
    }
    float t = tanhf(sacc + s_b1[lane]) * s_w2[lane];
#pragma unroll
    for (int oo = 16; oo; oo >>= 1) t += __shfl_xor_sync(0xffffffffu, t, oo);
    if (lane == 0) s_part[wid] = t;
    __syncthreads();
    if (tid == 0) {
        float s = 0.f;
#pragma unroll
        for (int i2 = 0; i2 < 32; i2++) s += s_part[i2];
        atomicAdd(&wsum[r], s);
    }
}

// ---------------- combine (beta inline) ----------------
__device__ __forceinline__ void beta_from_wsum(const float* ws, float& b0, float& b1, float& b2) {
    float w0 = ws[0] / NNODES, w1 = ws[1] / NNODES, w2 = ws[2] / NNODES;
    float m = fmaxf(w0, fmaxf(w1, w2));
    float e0 = __expf(w0 - m), e1 = __expf(w1 - m), e2 = __expf(w2 - m);
    float s = e0 + e1 + e2;
    b0 = e0 / s; b1 = e1 / s; b2 = e2 / s;
}

__global__ void k_combine_bf(const float* __restrict__ z, const float* __restrict__ ws,
                             __nv_bfloat16* __restrict__ hi, __nv_bfloat16* __restrict__ lo) {
    int idx = blockIdx.x * blockDim.x + threadIdx.x;
    if (idx >= NNODES * 32) return;
    float b0, b1, b2;
    beta_from_wsum(ws, b0, b1, b2);
    float4 z0 = *(const float4*)(z + (size_t)idx * 4);
    float4 z1 = *(const float4*)(z + (size_t)NNODES * 128 + (size_t)idx * 4);
    float4 z2 = *(const float4*)(z + (size_t)2 * NNODES * 128 + (size_t)idx * 4);
    float vx = b0 * z0.x + b1 * z1.x + b2 * z2.x;
    float vy = b0 * z0.y + b1 * z1.y + b2 * z2.y;
    float vz = b0 * z0.z + b1 * z1.z + b2 * z2.z;
    float vw = b0 * z0.w + b1 * z1.w + b2 * z2.w;
    __nv_bfloat16 h0 = __float2bfloat16(vx), h1 = __float2bfloat16(vy);
    __nv_bfloat16 h2 = __float2bfloat16(vz), h3 = __float2bfloat16(vw);
    ((__nv_bfloat162*)hi)[2 * idx]     = __nv_bfloat162(h0, h1);
    ((__nv_bfloat162*)hi)[2 * idx + 1] = __nv_bfloat162(h2, h3);
    ((__nv_bfloat162*)lo)[2 * idx]     = __nv_bfloat162(
        __float2bfloat16(vx - __bfloat162float(h0)), __float2bfloat16(vy - __bfloat162float(h1)));
    ((__nv_bfloat162*)lo)[2 * idx + 1] = __nv_bfloat162(
        __float2bfloat16(vz - __bfloat162float(h2)), __float2bfloat16(vw - __bfloat162float(h3)));
}

__global__ void k_combine_f32(const float* __restrict__ z, const float* __restrict__ ws,
                              float* __restrict__ out) {
    int idx = blockIdx.x * blockDim.x + threadIdx.x;
    if (idx >= NNODES * 32) return;
    float b0, b1, b2;
    beta_from_wsum(ws, b0, b1, b2);
    float4 z0 = *(const float4*)(z + (size_t)idx * 4);
    float4 z1 = *(const float4*)(z + (size_t)NNODES * 128 + (size_t)idx * 4);
    float4 z2 = *(const float4*)(z + (size_t)2 * NNODES * 128 + (size_t)idx * 4);
    float4 o;
    o.x = b0 * z0.x + b1 * z1.x + b2 * z2.x;
    o.y = b0 * z0.y + b1 * z1.y + b2 * z2.y;
    o.z = b0 * z0.z + b1 * z1.z + b2 * z2.z;
    o.w = b0 * z0.w + b1 * z1.w + b2 * z2.w;
    *(float4*)(out + (size_t)idx * 4) = o;
}

// ---------------- launch ----------------
extern "C" void kernel_launch(void* const* d_in, const int* in_sizes, int n_in,
                              void* d_out, int out_size) {
    const float* x     = (const float*)d_in[0];
    const int*   edges = (const int*)d_in[1];
    const float* W1  = (const float*)d_in[2];
    const float* al1 = (const float*)d_in[3];
    const float* ar1 = (const float*)d_in[4];
    const float* b1  = (const float*)d_in[5];
    const float* W2  = (const float*)d_in[6];
    const float* al2 = (const float*)d_in[7];
    const float* ar2 = (const float*)d_in[8];
    const float* b2  = (const float*)d_in[9];
    const float* aw1 = (const float*)d_in[10];
    const float* ab1 = (const float*)d_in[11];
    const float* aw2 = (const float*)d_in[12];
    const float* bw1 = (const float*)d_in[13];
    const float* bb1 = (const float*)d_in[14];
    const float* bw2 = (const float*)d_in[15];
    float* out = (float*)d_out;

    float *p_z, *p_el, *p_er, *p_ws;
    __half* p_fh;
    int *p_deg;
    __nv_bfloat16 *p_ahi, *p_alo, *p_whi, *p_wlo;
    cudaGetSymbolAddress((void**)&p_fh, g_fh);
    cudaGetSymbolAddress((void**)&p_z,  g_z);
    cudaGetSymbolAddress((void**)&p_el, g_el);
    cudaGetSymbolAddress((void**)&p_er, g_er);
    cudaGetSymbolAddress((void**)&p_ws, g_wsum);
    cudaGetSymbolAddress((void**)&p_deg, g_deg);
    cudaGetSymbolAddress((void**)&p_ahi, g_ahi);
    cudaGetSymbolAddress((void**)&p_alo, g_alo);
    cudaGetSymbolAddress((void**)&p_whi, g_whi);
    cudaGetSymbolAddress((void**)&p_wlo, g_wlo);

    cudaFuncSetAttribute(k_gemm_mma, cudaFuncAttributeMaxDynamicSharedMemorySize, SMEM_GEMM);
    cudaFuncSetAttribute(k_aggsc, cudaFuncAttributeMaxDynamicSharedMemorySize, SMEM_AGG);

    cudaMemsetAsync(p_deg, 0, NREL * NNODES * sizeof(int));
    cudaMemsetAsync(p_ws, 0, 2 * NREL * sizeof(float));
    k_build<<<dim3((NEDGES / 4 + 255) / 256, NREL), 256>>>(edges);
    k_cvtW<<<(2 * NREL * FDIM * FDIM + 255) / 256, 256>>>(W1, W2, p_whi, p_wlo);
    k_cvtA<<<(NNODES * 32 + 255) / 256, 256>>>(x, p_ahi, p_alo);

    const int ntiles = (NNODES + 127) / 128;                    // 157
    const dim3 gemm_grid((ntiles + MTILES - 1) / MTILES, NREL); // (53, 3)
    const dim3 agg_grid(NNODES / 32, NREL);                     // (625, 3)

    // ---- layer 1 ----
    k_gemm_mma<<<gemm_grid, 512, SMEM_GEMM>>>(p_ahi, p_alo, p_whi, p_wlo,
                                              al1, ar1, p_fh, p_el, p_er);
    k_aggsc<<<agg_grid, 1024, SMEM_AGG>>>(p_fh, p_el, p_er, b1, aw1, ab1, aw2, p_ws, p_z, 1);
    k_combine_bf<<<(NNODES * 32 + 255) / 256, 256>>>(p_z, p_ws, p_ahi, p_alo);

    // ---- layer 2 ----
    k_gemm_mma<<<gemm_grid, 512, SMEM_GEMM>>>(p_ahi, p_alo,
                                              p_whi + (size_t)NREL * FDIM * FDIM,
                                              p_wlo + (size_t)NREL * FDIM * FDIM,
                                              al2, ar2, p_fh, p_el, p_er);
    k_aggsc<<<agg_grid, 1024, SMEM_AGG>>>(p_fh, p_el, p_er, b2, bw1, bb1, bw2, p_ws + NREL, p_z, 0);
    k_combine_f32<<<(NNODES * 32 + 255) / 256, 256>>>(p_z, p_ws + NREL, out);
}

// round 17
// speedup vs baseline: 1.6097x; 1.6097x over previous
#include <cuda_runtime.h>
#include <cuda_bf16.h>
#include <cuda_fp16.h>
#include <cstdint>
#include <math.h>

#define NNODES 20000
#define NEDGES 320000
#define NREL 3
#define FDIM 128
#define NEG_SLOPE 0.2f
#define CAP 96          // bucket capacity per (relation, dst)

// ---------------- scratch (static device globals; no allocation) ----------------
__device__ __half g_fh[(size_t)NREL * NNODES * FDIM];   // f in fp16 (gather payload)
__device__ float g_z[(size_t)NREL * NNODES * FDIM];
__device__ float g_el[NREL * NNODES * 2];
__device__ float g_er[NREL * NNODES * 2];
__device__ int   g_deg[NREL * NNODES];
__device__ int   g_bkt[(size_t)NREL * NNODES * CAP];
__device__ float g_wsum[2 * NREL];
// bf16 split operands
__device__ __nv_bfloat16 g_ahi[(size_t)NNODES * FDIM];
__device__ __nv_bfloat16 g_alo[(size_t)NNODES * FDIM];
__device__ __nv_bfloat16 g_whi[2 * NREL * FDIM * FDIM];   // [layer][r][n][k]
__device__ __nv_bfloat16 g_wlo[2 * NREL * FDIM * FDIM];

// ---------------- fused bucket build ----------------
__global__ void k_build(const int* __restrict__ edges) {
    int r = blockIdx.y;
    int t = blockIdx.x * blockDim.x + threadIdx.x;
    if (t >= NEDGES / 4) return;
    const int4 s4 = *(const int4*)(edges + (size_t)(r * 2 + 0) * NEDGES + 4 * t);
    const int4 d4 = *(const int4*)(edges + (size_t)(r * 2 + 1) * NEDGES + 4 * t);
    int base = r * NNODES;
    int p0 = atomicAdd(&g_deg[base + d4.x], 1);
    int p1 = atomicAdd(&g_deg[base + d4.y], 1);
    int p2 = atomicAdd(&g_deg[base + d4.z], 1);
    int p3 = atomicAdd(&g_deg[base + d4.w], 1);
    g_bkt[(size_t)(base + d4.x) * CAP + p0] = s4.x;
    g_bkt[(size_t)(base + d4.y) * CAP + p1] = s4.y;
    g_bkt[(size_t)(base + d4.z) * CAP + p2] = s4.z;
    g_bkt[(size_t)(base + d4.w) * CAP + p3] = s4.w;
}

// ---------------- bf16 split conversion ----------------
__global__ void k_cvtA(const float* __restrict__ src,
                       __nv_bfloat16* __restrict__ hi, __nv_bfloat16* __restrict__ lo) {
    int i = blockIdx.x * blockDim.x + threadIdx.x;
    if (i >= NNODES * 32) return;
    float4 v = ((const float4*)src)[i];
    __nv_bfloat16 h0 = __float2bfloat16(v.x), h1 = __float2bfloat16(v.y);
    __nv_bfloat16 h2 = __float2bfloat16(v.z), h3 = __float2bfloat16(v.w);
    ((__nv_bfloat162*)hi)[2 * i]     = __nv_bfloat162(h0, h1);
    ((__nv_bfloat162*)hi)[2 * i + 1] = __nv_bfloat162(h2, h3);
    ((__nv_bfloat162*)lo)[2 * i]     = __nv_bfloat162(
        __float2bfloat16(v.x - __bfloat162float(h0)), __float2bfloat16(v.y - __bfloat162float(h1)));
    ((__nv_bfloat162*)lo)[2 * i + 1] = __nv_bfloat162(
        __float2bfloat16(v.z - __bfloat162float(h2)), __float2bfloat16(v.w - __bfloat162float(h3)));
}

__global__ void k_cvtW(const float* __restrict__ W1, const float* __restrict__ W2,
                       __nv_bfloat16* __restrict__ hi, __nv_bfloat16* __restrict__ lo) {
    int idx = blockIdx.x * blockDim.x + threadIdx.x;
    if (idx >= 2 * NREL * FDIM * FDIM) return;
    int l = idx / (NREL * FDIM * FDIM);
    int rem = idx - l * (NREL * FDIM * FDIM);
    int r = rem >> 14;
    int n = (rem >> 7) & 127, k = rem & 127;
    const float* W = l ? W2 : W1;
    float v = W[r * 16384 + k * 128 + n];
    __nv_bfloat16 h = __float2bfloat16(v);
    hi[idx] = h;
    lo[idx] = __float2bfloat16(v - __bfloat162float(h));
}

// ---------------- mma.sync GEMM (round-15 frozen version) ----------------
#define ASTRIDE 136
#define TILEB  (128 * ASTRIDE)
#define TILEBYTES (TILEB * 2)
#define SMEM_GEMM (4 * TILEBYTES + 2 * 128 * 4)

__device__ __forceinline__ uint32_t smem_u32(const void* p) {
    uint32_t a;
    asm("{ .reg .u64 t; cvta.to.shared.u64 t, %1; cvt.u32.u64 %0, t; }" : "=r"(a) : "l"(p));
    return a;
}
__device__ __forceinline__ void cp16(uint32_t dst, const void* src, int sz) {
    asm volatile("cp.async.cg.shared.global [%0], [%1], 16, %2;"
                 :: "r"(dst), "l"(src), "r"(sz));
}
__device__ __forceinline__ void ldsm_x4(uint32_t addr, uint32_t& r0, uint32_t& r1,
                                        uint32_t& r2, uint32_t& r3) {
    asm volatile("ldmatrix.sync.aligned.m8n8.x4.shared.b16 {%0,%1,%2,%3}, [%4];"
                 : "=r"(r0), "=r"(r1), "=r"(r2), "=r"(r3) : "r"(addr));
}
__device__ __forceinline__ void ldsm_x2(uint32_t addr, uint32_t& r0, uint32_t& r1) {
    asm volatile("ldmatrix.sync.aligned.m8n8.x2.shared.b16 {%0,%1}, [%2];"
                 : "=r"(r0), "=r"(r1) : "r"(addr));
}
__device__ __forceinline__ void mma16816(float* c, uint32_t a0, uint32_t a1, uint32_t a2,
                                         uint32_t a3, uint32_t b0, uint32_t b1) {
    asm volatile(
        "mma.sync.aligned.m16n8k16.row.col.f32.bf16.bf16.f32 "
        "{%0,%1,%2,%3}, {%4,%5,%6,%7}, {%8,%9}, {%0,%1,%2,%3};"
        : "+f"(c[0]), "+f"(c[1]), "+f"(c[2]), "+f"(c[3])
        : "r"(a0), "r"(a1), "r"(a2), "r"(a3), "r"(b0), "r"(b1));
}

// 512 threads = 16 warps: 8 M-warps x 2 N-warps. Warp tile 16 rows x 64 cols.
__global__ void __launch_bounds__(512) k_gemm_mma(
    const __nv_bfloat16* __restrict__ ahi, const __nv_bfloat16* __restrict__ alo,
    const __nv_bfloat16* __restrict__ whi, const __nv_bfloat16* __restrict__ wlo,
    const float* __restrict__ alv, const float* __restrict__ arv,
    __half* __restrict__ fh_base, float* __restrict__ el_base, float* __restrict__ er_base) {
    extern __shared__ char smem[];
    __nv_bfloat16* Ah = (__nv_bfloat16*)smem;
    __nv_bfloat16* Al = Ah + TILEB;
    __nv_bfloat16* Bh = Al + TILEB;
    __nv_bfloat16* Bl = Bh + TILEB;
    float* s_al = (float*)(Bl + TILEB);
    float* s_ar = s_al + 128;
    uint32_t sb = smem_u32(smem);

    int tid = threadIdx.x;
    int wid = tid >> 5, lane = tid & 31;
    int wid_m = wid & 7, wid_n = wid >> 3;
    int r = blockIdx.y;
    int m0 = blockIdx.x * 128;

    __half* fh = fh_base + (size_t)r * NNODES * FDIM;
    float* el = el_base + r * NNODES * 2;
    float* er = er_base + r * NNODES * 2;

    if (tid < 128) { s_al[tid] = alv[r * 128 + tid]; s_ar[tid] = arv[r * 128 + tid]; }

    // ---- cp.async fill ----
    const __nv_bfloat16* wh = whi + (size_t)r * 16384;
    const __nv_bfloat16* wl = wlo + (size_t)r * 16384;
    for (int c = tid; c < 2048; c += 512) {
        int row = c >> 4;
        int col = (c & 15) << 3;
        int gm = m0 + row;
        int sz = (gm < NNODES) ? 16 : 0;
        int gmc = (gm < NNODES) ? gm : (NNODES - 1);
        uint32_t soff = (uint32_t)(row * ASTRIDE + col) * 2;
        cp16(sb + soff,                 ahi + (size_t)gmc * 128 + col, sz);
        cp16(sb + TILEBYTES + soff,     alo + (size_t)gmc * 128 + col, sz);
        cp16(sb + 2 * TILEBYTES + soff, wh + row * 128 + col, 16);
        cp16(sb + 3 * TILEBYTES + soff, wl + row * 128 + col, 16);
    }
    asm volatile("cp.async.commit_group;");
    asm volatile("cp.async.wait_group 0;" ::: "memory");
    __syncthreads();

    // ---- MMA mainloop ----
    int m_base = wid_m * 16;
    int cb = wid_n * 64;
    float acc[8][4];
#pragma unroll
    for (int nt = 0; nt < 8; nt++)
#pragma unroll
        for (int j = 0; j < 4; j++) acc[nt][j] = 0.f;

    uint32_t a_row = (uint32_t)(m_base + (lane & 15));
    uint32_t a_colsel = (uint32_t)((lane >> 4) << 3);
    uint32_t b_row = (uint32_t)(cb + (lane & 7));
    uint32_t b_colsel = (uint32_t)(((lane >> 3) & 1) << 3);

#pragma unroll
    for (int t = 0; t < 3; t++) {
        const __nv_bfloat16* As = (t < 2) ? Ah : Al;
        const __nv_bfloat16* Bs = (t == 1) ? Bl : Bh;
        uint32_t a_base = smem_u32(As + a_row * ASTRIDE + a_colsel);
        uint32_t b_base = smem_u32(Bs + b_row * ASTRIDE + b_colsel);
#pragma unroll
        for (int kk = 0; kk < 8; kk++) {
            uint32_t a0, a1, a2, a3;
            ldsm_x4(a_base + kk * 32, a0, a1, a2, a3);
#pragma unroll
            for (int nt = 0; nt < 8; nt++) {
                uint32_t b0, b1;
                ldsm_x2(b_base + (uint32_t)(nt * 8 * ASTRIDE * 2) + kk * 32, b0, b1);
                mma16816(acc[nt], a0, a1, a2, a3, b0, b1);
            }
        }
    }

    // ---- epilogue: fused el/er (head = wid_n, warp-local) + fp16 f stores ----
    int q = lane & 3;
    int r0 = m_base + (lane >> 2);
    int r1 = r0 + 8;
    int gm0 = m0 + r0, gm1 = m0 + r1;
    float elA = 0.f, erA = 0.f, elB = 0.f, erB = 0.f;
#pragma unroll
    for (int nt = 0; nt < 8; nt++) {
        int c0 = cb + nt * 8 + q * 2;
        float a0 = s_al[c0], a1 = s_al[c0 + 1];
        float b0 = s_ar[c0], b1 = s_ar[c0 + 1];
        elA += acc[nt][0] * a0 + acc[nt][1] * a1;
        elB += acc[nt][2] * a0 + acc[nt][3] * a1;
        erA += acc[nt][0] * b0 + acc[nt][1] * b1;
        erB += acc[nt][2] * b0 + acc[nt][3] * b1;
        if (gm0 < NNODES)
            *(__half2*)(fh + (size_t)gm0 * 128 + c0) =
                __float22half2_rn(make_float2(acc[nt][0], acc[nt][1]));
        if (gm1 < NNODES)
            *(__half2*)(fh + (size_t)gm1 * 128 + c0) =
                __float22half2_rn(make_float2(acc[nt][2], acc[nt][3]));
    }
#pragma unroll
    for (int o = 1; o <= 2; o <<= 1) {
        elA += __shfl_xor_sync(0xffffffffu, elA, o);
        erA += __shfl_xor_sync(0xffffffffu, erA, o);
        elB += __shfl_xor_sync(0xffffffffu, elB, o);
        erB += __shfl_xor_sync(0xffffffffu, erB, o);
    }
    if (q == 0) {
        if (gm0 < NNODES) { el[2 * gm0 + wid_n] = elA; er[2 * gm0 + wid_n] = erA; }
        if (gm1 < NNODES) { el[2 * gm1 + wid_n] = elB; er[2 * gm1 + wid_n] = erB; }
    }
}

// ---------------- GAT aggregation + fused semantic score (round-16 winner) ----------------
// smem: w1 16384 | b1 128 | w2 128 | part 128 | src 12288 | wgt 24576 | z 16384
#define AG_W1   0
#define AG_B1   16384
#define AG_W2   16512
#define AG_PART 16640
#define AG_SRC  16768
#define AG_WGT  (16768 + 12288)
#define AG_Z    (16768 + 12288 + 24576)
#define SMEM_AGG (AG_Z + 16384)

__global__ void __launch_bounds__(1024) k_aggsc(
    const __half* __restrict__ fh_base, const float* __restrict__ el_base,
    const float* __restrict__ er_base, const float* __restrict__ bias_base,
    const float* __restrict__ w1, const float* __restrict__ bb,
    const float* __restrict__ w2, float* __restrict__ wsum,
    float* __restrict__ z_base, int do_relu) {
    extern __shared__ char sm[];
    float* s_w1  = (float*)(sm + AG_W1);
    float* s_b1  = (float*)(sm + AG_B1);
    float* s_w2  = (float*)(sm + AG_W2);
    float* s_part= (float*)(sm + AG_PART);
    int*   s_src = (int*)(sm + AG_SRC);
    float* s_wgt = (float*)(sm + AG_WGT);
    float* s_z   = (float*)(sm + AG_Z);

    int r = blockIdx.y;
    const __half* fh = fh_base + (size_t)r * NNODES * FDIM;
    const float* el  = el_base + r * NNODES * 2;
    const float* er  = er_base + r * NNODES * 2;
    const float* bias = bias_base + r * 128;
    float* z = z_base + (size_t)r * NNODES * FDIM;

    int tid = threadIdx.x;
    ((float4*)s_w1)[tid] = ((const float4*)w1)[tid];     // 1024 float4 = 4096 floats
    if (tid < 32) { s_b1[tid] = bb[tid]; s_w2[tid] = w2[tid]; }
    __syncthreads();

    int wid = tid >> 5, lane = tid & 31;
    int n = blockIdx.x * 32 + wid;
    int deg = g_deg[r * NNODES + n];
    const int* bkt = &g_bkt[(size_t)(r * NNODES + n) * CAP];
    float er0 = er[2 * n], er1 = er[2 * n + 1];

    // ---- phase A: per-edge weights, lane-parallel ----
    float den0 = 0.f, den1 = 0.f;
    for (int i = lane; i < deg; i += 32) {
        int s = bkt[i];
        float2 ev = *(const float2*)(el + 2 * s);
        float e0 = ev.x + er0; e0 = e0 > 0.f ? e0 : NEG_SLOPE * e0;
        float e1 = ev.y + er1; e1 = e1 > 0.f ? e1 : NEG_SLOPE * e1;
        float w0 = __expf(e0), w1v = __expf(e1);
        s_src[wid * CAP + i] = s;
        s_wgt[(wid * 2 + 0) * CAP + i] = w0;
        s_wgt[(wid * 2 + 1) * CAP + i] = w1v;
        den0 += w0; den1 += w1v;
    }
#pragma unroll
    for (int o = 16; o; o >>= 1) {
        den0 += __shfl_xor_sync(0xffffffffu, den0, o);
        den1 += __shfl_xor_sync(0xffffffffu, den1, o);
    }
    __syncwarp();

    // ---- phase B: serial accumulate, 8B fp16 gathers ----
    int myh = lane >> 4;
    const float* wgt = &s_wgt[(wid * 2 + myh) * CAP];
    const int* src = &s_src[wid * CAP];
    float4 acc = make_float4(0.f, 0.f, 0.f, 0.f);
#pragma unroll 4
    for (int i = 0; i < deg; i++) {
        int s = src[i];
        float w = wgt[i];
        uint2 raw = *(const uint2*)(fh + (size_t)s * 128 + lane * 4);
        float2 a = __half22float2(*(const __half2*)&raw.x);
        float2 b = __half22float2(*(const __half2*)&raw.y);
        acc.x += w * a.x; acc.y += w * a.y; acc.z += w * b.x; acc.w += w * b.y;
    }
    float den = myh ? den1 : den0;
    float scale = 1.f / fmaxf(den, 1e-9f);
    float4 bv = *(const float4*)(bias + lane * 4);
    float4 o;
    o.x = acc.x * scale + bv.x;
    o.y = acc.y * scale + bv.y;
    o.z = acc.z * scale + bv.z;
    o.w = acc.w * scale + bv.w;
    if (do_relu) {
        o.x = fmaxf(o.x, 0.f); o.y = fmaxf(o.y, 0.f);
        o.z = fmaxf(o.z, 0.f); o.w = fmaxf(o.w, 0.f);
    }
    *(float4*)(z + (size_t)n * 128 + lane * 4) = o;

    // ---- fused semantic score: z staged in smem (warp-local), no shfl ----
    *(float4*)(s_z + wid * 128 + lane * 4) = o;
    __syncwarp();
    float sacc = 0.f;
    const float* zrow = s_z + wid * 128;
#pragma unroll
    for (int k4 = 0; k4 < 32; k4++) {
        float4 zv = *(const float4*)(zrow + k4 * 4);
        sacc += zv.x * s_w1[(k4 * 4 + 0) * 32 + lane]
              + zv.y * s_w1[(k4 * 4 + 1) * 32 + lane]
              + zv.z * s_w1[(k4 * 4 + 2) * 32 + lane]
              + zv.w * s_w1[(k4 * 4 + 3) * 32 + lane];
    }
    float t = tanhf(sacc + s_b1[lane]) * s_w2[lane];
#pragma unroll
    for (int oo = 16; oo; oo >>= 1) t += __shfl_xor_sync(0xffffffffu, t, oo);
    if (lane == 0) s_part[wid] = t;
    __syncthreads();
    if (tid == 0) {
        float s = 0.f;
#pragma unroll
        for (int i2 = 0; i2 < 32; i2++) s += s_part[i2];
        atomicAdd(&wsum[r], s);
    }
}

// ---------------- combine (beta inline) ----------------
__device__ __forceinline__ void beta_from_wsum(const float* ws, float& b0, float& b1, float& b2) {
    float w0 = ws[0] / NNODES, w1 = ws[1] / NNODES, w2 = ws[2] / NNODES;
    float m = fmaxf(w0, fmaxf(w1, w2));
    float e0 = __expf(w0 - m), e1 = __expf(w1 - m), e2 = __expf(w2 - m);
    float s = e0 + e1 + e2;
    b0 = e0 / s; b1 = e1 / s; b2 = e2 / s;
}

__global__ void k_combine_bf(const float* __restrict__ z, const float* __restrict__ ws,
                             __nv_bfloat16* __restrict__ hi, __nv_bfloat16* __restrict__ lo) {
    int idx = blockIdx.x * blockDim.x + threadIdx.x;
    if (idx >= NNODES * 32) return;
    float b0, b1, b2;
    beta_from_wsum(ws, b0, b1, b2);
    float4 z0 = *(const float4*)(z + (size_t)idx * 4);
    float4 z1 = *(const float4*)(z + (size_t)NNODES * 128 + (size_t)idx * 4);
    float4 z2 = *(const float4*)(z + (size_t)2 * NNODES * 128 + (size_t)idx * 4);
    float vx = b0 * z0.x + b1 * z1.x + b2 * z2.x;
    float vy = b0 * z0.y + b1 * z1.y + b2 * z2.y;
    float vz = b0 * z0.z + b1 * z1.z + b2 * z2.z;
    float vw = b0 * z0.w + b1 * z1.w + b2 * z2.w;
    __nv_bfloat16 h0 = __float2bfloat16(vx), h1 = __float2bfloat16(vy);
    __nv_bfloat16 h2 = __float2bfloat16(vz), h3 = __float2bfloat16(vw);
    ((__nv_bfloat162*)hi)[2 * idx]     = __nv_bfloat162(h0, h1);
    ((__nv_bfloat162*)hi)[2 * idx + 1] = __nv_bfloat162(h2, h3);
    ((__nv_bfloat162*)lo)[2 * idx]     = __nv_bfloat162(
        __float2bfloat16(vx - __bfloat162float(h0)), __float2bfloat16(vy - __bfloat162float(h1)));
    ((__nv_bfloat162*)lo)[2 * idx + 1] = __nv_bfloat162(
        __float2bfloat16(vz - __bfloat162float(h2)), __float2bfloat16(vw - __bfloat162float(h3)));
}

__global__ void k_combine_f32(const float* __restrict__ z, const float* __restrict__ ws,
                              float* __restrict__ out) {
    int idx = blockIdx.x * blockDim.x + threadIdx.x;
    if (idx >= NNODES * 32) return;
    float b0, b1, b2;
    beta_from_wsum(ws, b0, b1, b2);
    float4 z0 = *(const float4*)(z + (size_t)idx * 4);
    float4 z1 = *(const float4*)(z + (size_t)NNODES * 128 + (size_t)idx * 4);
    float4 z2 = *(const float4*)(z + (size_t)2 * NNODES * 128 + (size_t)idx * 4);
    float4 o;
    o.x = b0 * z0.x + b1 * z1.x + b2 * z2.x;
    o.y = b0 * z0.y + b1 * z1.y + b2 * z2.y;
    o.z = b0 * z0.z + b1 * z1.z + b2 * z2.z;
    o.w = b0 * z0.w + b1 * z1.w + b2 * z2.w;
    *(float4*)(out + (size_t)idx * 4) = o;
}

// ---------------- launch ----------------
extern "C" void kernel_launch(void* const* d_in, const int* in_sizes, int n_in,
                              void* d_out, int out_size) {
    const float* x     = (const float*)d_in[0];
    const int*   edges = (const int*)d_in[1];
    const float* W1  = (const float*)d_in[2];
    const float* al1 = (const float*)d_in[3];
    const float* ar1 = (const float*)d_in[4];
    const float* b1  = (const float*)d_in[5];
    const float* W2  = (const float*)d_in[6];
    const float* al2 = (const float*)d_in[7];
    const float* ar2 = (const float*)d_in[8];
    const float* b2  = (const float*)d_in[9];
    const float* aw1 = (const float*)d_in[10];
    const float* ab1 = (const float*)d_in[11];
    const float* aw2 = (const float*)d_in[12];
    const float* bw1 = (const float*)d_in[13];
    const float* bb1 = (const float*)d_in[14];
    const float* bw2 = (const float*)d_in[15];
    float* out = (float*)d_out;

    float *p_z, *p_el, *p_er, *p_ws;
    __half* p_fh;
    int *p_deg;
    __nv_bfloat16 *p_ahi, *p_alo, *p_whi, *p_wlo;
    cudaGetSymbolAddress((void**)&p_fh, g_fh);
    cudaGetSymbolAddress((void**)&p_z,  g_z);
    cudaGetSymbolAddress((void**)&p_el, g_el);
    cudaGetSymbolAddress((void**)&p_er, g_er);
    cudaGetSymbolAddress((void**)&p_ws, g_wsum);
    cudaGetSymbolAddress((void**)&p_deg, g_deg);
    cudaGetSymbolAddress((void**)&p_ahi, g_ahi);
    cudaGetSymbolAddress((void**)&p_alo, g_alo);
    cudaGetSymbolAddress((void**)&p_whi, g_whi);
    cudaGetSymbolAddress((void**)&p_wlo, g_wlo);

    cudaFuncSetAttribute(k_gemm_mma, cudaFuncAttributeMaxDynamicSharedMemorySize, SMEM_GEMM);
    cudaFuncSetAttribute(k_aggsc, cudaFuncAttributeMaxDynamicSharedMemorySize, SMEM_AGG);

    cudaMemsetAsync(p_deg, 0, NREL * NNODES * sizeof(int));
    cudaMemsetAsync(p_ws, 0, 2 * NREL * sizeof(float));
    k_build<<<dim3((NEDGES / 4 + 255) / 256, NREL), 256>>>(edges);
    k_cvtW<<<(2 * NREL * FDIM * FDIM + 255) / 256, 256>>>(W1, W2, p_whi, p_wlo);
    k_cvtA<<<(NNODES * 32 + 255) / 256, 256>>>(x, p_ahi, p_alo);

    const dim3 gemm_grid((NNODES + 127) / 128, NREL);   // (157, 3)
    const dim3 agg_grid(NNODES / 32, NREL);             // (625, 3)

    // ---- layer 1 ----
    k_gemm_mma<<<gemm_grid, 512, SMEM_GEMM>>>(p_ahi, p_alo, p_whi, p_wlo,
                                              al1, ar1, p_fh, p_el, p_er);
    k_aggsc<<<agg_grid, 1024, SMEM_AGG>>>(p_fh, p_el, p_er, b1, aw1, ab1, aw2, p_ws, p_z, 1);
    k_combine_bf<<<(NNODES * 32 + 255) / 256, 256>>>(p_z, p_ws, p_ahi, p_alo);

    // ---- layer 2 ----
    k_gemm_mma<<<gemm_grid, 512, SMEM_GEMM>>>(p_ahi, p_alo,
                                              p_whi + (size_t)NREL * FDIM * FDIM,
                                              p_wlo + (size_t)NREL * FDIM * FDIM,
                                              al2, ar2, p_fh, p_el, p_er);
    k_aggsc<<<agg_grid, 1024, SMEM_AGG>>>(p_fh, p_el, p_er, b2, bw1, bb1, bw2, p_ws + NREL, p_z, 0);
    k_combine_f32<<<(NNODES * 32 + 255) / 256, 256>>>(p_z, p_ws + NREL, out);
}